// round 5
// baseline (speedup 1.0000x reference)
#include <cuda_runtime.h>

// Problem constants
#define BB 2048
#define TT 200
#define DD 4
#define HH 256
#define GG 1024        // 4*H, gate order i,f,g,o
#define MM 16          // batch rows per CTA
#define NCTA (BB / MM) // 128 CTAs
#define MH 8           // rows per thread (one batch half)
#define OO 6
#define HROW 18        // u64 (dup-pair) slots per h row: 16 used + 2 pad (144B, 16B-aligned)
#define SH_LAYER (2 * HH * HROW)  // u64 count for one double-buffered layer

typedef unsigned long long u64;

// Gate-pair-interleaved transposed weights: [k][pp][j], pp=0 -> (w_i,w_f), pp=1 -> (w_g,w_o)
__device__ u64 g_Wp_hh0[HH * 2 * HH];
__device__ u64 g_Wp_ih1[HH * 2 * HH];
__device__ u64 g_Wp_hh1[HH * 2 * HH];
__device__ float g_b0[GG];
__device__ float g_b1[GG];

// ---- packed f32x2 helpers ----
__device__ __forceinline__ u64 fma2(u64 a, u64 b, u64 c) {
    u64 d;
    asm("fma.rn.f32x2 %0, %1, %2, %3;" : "=l"(d) : "l"(a), "l"(b), "l"(c));
    return d;
}
__device__ __forceinline__ u64 pack2(float a, float b) {
    u64 d;
    asm("mov.b64 %0, {%1, %2};" : "=l"(d)
        : "r"(__float_as_uint(a)), "r"(__float_as_uint(b)));
    return d;
}
__device__ __forceinline__ void unpack2(u64 v, float& a, float& b) {
    unsigned x, y;
    asm("mov.b64 {%0, %1}, %2;" : "=r"(x), "=r"(y) : "l"(v));
    a = __uint_as_float(x);
    b = __uint_as_float(y);
}
__device__ __forceinline__ float sigf(float x) {
    return 1.0f / (1.0f + __expf(-x));
}

// -------- prep: build gate-pair-interleaved transposed weights + combined biases --------
__global__ void prep_kernel(const float* __restrict__ W_hh0,
                            const float* __restrict__ W_ih1,
                            const float* __restrict__ W_hh1,
                            const float* __restrict__ b_ih0,
                            const float* __restrict__ b_hh0,
                            const float* __restrict__ b_ih1,
                            const float* __restrict__ b_hh1) {
    int idx = blockIdx.x * blockDim.x + threadIdx.x;
    int stride = gridDim.x * blockDim.x;
    for (int t = idx; t < HH * 2 * HH; t += stride) {
        int j = t & (HH - 1);
        int pp = (t >> 8) & 1;
        int k = t >> 9;
        int g0 = 2 * pp * HH + j;   // gate i (pp=0) or g (pp=1)
        int g1 = g0 + HH;           // gate f (pp=0) or o (pp=1)
        g_Wp_hh0[t] = pack2(W_hh0[g0 * HH + k], W_hh0[g1 * HH + k]);
        g_Wp_ih1[t] = pack2(W_ih1[g0 * HH + k], W_ih1[g1 * HH + k]);
        g_Wp_hh1[t] = pack2(W_hh1[g0 * HH + k], W_hh1[g1 * HH + k]);
    }
    if (idx < GG) {
        g_b0[idx] = b_ih0[idx] + b_hh0[idx];
        g_b1[idx] = b_ih1[idx] + b_hh1[idx];
    }
}

// -------- main LSTM kernel: 512 threads = 256 hidden units x 2 batch halves --------
__global__ __launch_bounds__(512, 1)
void lstm_kernel(const float* __restrict__ x,
                 const float* __restrict__ W_ih0,
                 const float* __restrict__ W_fc,
                 const float* __restrict__ b_fc,
                 float* __restrict__ out) {
    extern __shared__ u64 dsm[];
    u64* sh1 = dsm;                    // [2][HH][HROW] layer0 h, dup pairs
    u64* sh2 = dsm + SH_LAYER;         // [2][HH][HROW] layer1 h
    float* xs = (float*)(dsm + 2 * SH_LAYER);  // [MM][DD]

    const int tid  = threadIdx.x;
    const int j    = tid & (HH - 1);   // hidden unit
    const int half = tid >> 8;         // batch half (warp-uniform)
    const int mb   = half * MH;        // first row (= dup-pair slot) for this thread
    const int row0 = blockIdx.x * MM;

    // Per-thread constants
    float wih0[4][DD];
    float bi0 = g_b0[j], bf0 = g_b0[j + HH], bg0 = g_b0[j + 2 * HH], bo0 = g_b0[j + 3 * HH];
    float bi1 = g_b1[j], bf1 = g_b1[j + HH], bg1 = g_b1[j + 2 * HH], bo1 = g_b1[j + 3 * HH];
#pragma unroll
    for (int q = 0; q < 4; q++)
#pragma unroll
        for (int d = 0; d < DD; d++)
            wih0[q][d] = W_ih0[(j + q * HH) * DD + d];

    float c1[MH], c2[MH];
#pragma unroll
    for (int m = 0; m < MH; m++) {
        c1[m] = 0.0f;
        c2[m] = 0.0f;
        sh1[j * HROW + mb + m] = 0ull;   // buffer 0
        sh2[j * HROW + mb + m] = 0ull;
    }

    // prefetch x for t=0
    float xreg = 0.0f;
    if (tid < MM * DD)
        xreg = x[(row0 + (tid >> 2)) * (TT * DD) + (tid & 3)];
    __syncthreads();

    for (int t = 0; t < TT; t++) {
        const int inb = t & 1;
        const int outb = inb ^ 1;
        const u64* h1in = sh1 + inb * (HH * HROW);
        u64* h1out      = sh1 + outb * (HH * HROW);
        const u64* h2in = sh2 + inb * (HH * HROW);
        u64* h2out      = sh2 + outb * (HH * HROW);

        if (tid < MM * DD) xs[tid] = xreg;
        __syncthreads();  // B1: xs + prev-step h2 writes visible

        // ================= Layer 0 =================
        u64 aif[MH], ago[MH];
#pragma unroll
        for (int m = 0; m < MH; m++) {
            float zi = bi0, zf = bf0, zg = bg0, zo = bo0;
#pragma unroll
            for (int d = 0; d < DD; d++) {
                float xv = xs[(mb + m) * DD + d];
                zi = fmaf(wih0[0][d], xv, zi);
                zf = fmaf(wih0[1][d], xv, zf);
                zg = fmaf(wih0[2][d], xv, zg);
                zo = fmaf(wih0[3][d], xv, zo);
            }
            aif[m] = pack2(zi, zf);
            ago[m] = pack2(zg, zo);
        }

        {
            const u64* p = g_Wp_hh0 + j;
#pragma unroll 4
            for (int k = 0; k < HH; k++) {
                u64 wif = p[0];
                u64 wgo = p[HH];
                p += 2 * HH;
                const longlong2* hr = (const longlong2*)(h1in + k * HROW + mb);
                longlong2 h01 = hr[0], h23 = hr[1], h45 = hr[2], h67 = hr[3];
                aif[0] = fma2(wif, (u64)h01.x, aif[0]); ago[0] = fma2(wgo, (u64)h01.x, ago[0]);
                aif[1] = fma2(wif, (u64)h01.y, aif[1]); ago[1] = fma2(wgo, (u64)h01.y, ago[1]);
                aif[2] = fma2(wif, (u64)h23.x, aif[2]); ago[2] = fma2(wgo, (u64)h23.x, ago[2]);
                aif[3] = fma2(wif, (u64)h23.y, aif[3]); ago[3] = fma2(wgo, (u64)h23.y, ago[3]);
                aif[4] = fma2(wif, (u64)h45.x, aif[4]); ago[4] = fma2(wgo, (u64)h45.x, ago[4]);
                aif[5] = fma2(wif, (u64)h45.y, aif[5]); ago[5] = fma2(wgo, (u64)h45.y, ago[5]);
                aif[6] = fma2(wif, (u64)h67.x, aif[6]); ago[6] = fma2(wgo, (u64)h67.x, ago[6]);
                aif[7] = fma2(wif, (u64)h67.y, aif[7]); ago[7] = fma2(wgo, (u64)h67.y, ago[7]);
            }
        }

        // activations + cell update, write dup'd h1
#pragma unroll
        for (int m = 0; m < MH; m++) {
            float zi, zf, zg, zo;
            unpack2(aif[m], zi, zf);
            unpack2(ago[m], zg, zo);
            float ig = sigf(zi), fg = sigf(zf), gg = tanhf(zg), og = sigf(zo);
            float c = fmaf(fg, c1[m], ig * gg);
            c1[m] = c;
            float h = og * tanhf(c);
            h1out[j * HROW + mb + m] = pack2(h, h);
        }

        // prefetch x for t+1 (hidden under layer-1 compute)
        if (tid < MM * DD && t + 1 < TT)
            xreg = x[(row0 + (tid >> 2)) * (TT * DD) + (t + 1) * DD + (tid & 3)];

        __syncthreads();  // B2: h1out visible

        // ================= Layer 1 =================
#pragma unroll
        for (int m = 0; m < MH; m++) {
            aif[m] = pack2(bi1, bf1);
            ago[m] = pack2(bg1, bo1);
        }

        {
            const u64* pi = g_Wp_ih1 + j;
            const u64* ph = g_Wp_hh1 + j;
#pragma unroll 2
            for (int k = 0; k < HH; k++) {
                u64 wiif = pi[0];
                u64 wigo = pi[HH];
                pi += 2 * HH;
                u64 whif = ph[0];
                u64 whgo = ph[HH];
                ph += 2 * HH;
                const longlong2* ar = (const longlong2*)(h1out + k * HROW + mb);
                const longlong2* br = (const longlong2*)(h2in + k * HROW + mb);
                longlong2 a01 = ar[0], a23 = ar[1], a45 = ar[2], a67 = ar[3];
                longlong2 b01 = br[0], b23 = br[1], b45 = br[2], b67 = br[3];
                aif[0] = fma2(wiif, (u64)a01.x, aif[0]); ago[0] = fma2(wigo, (u64)a01.x, ago[0]);
                aif[0] = fma2(whif, (u64)b01.x, aif[0]); ago[0] = fma2(whgo, (u64)b01.x, ago[0]);
                aif[1] = fma2(wiif, (u64)a01.y, aif[1]); ago[1] = fma2(wigo, (u64)a01.y, ago[1]);
                aif[1] = fma2(whif, (u64)b01.y, aif[1]); ago[1] = fma2(whgo, (u64)b01.y, ago[1]);
                aif[2] = fma2(wiif, (u64)a23.x, aif[2]); ago[2] = fma2(wigo, (u64)a23.x, ago[2]);
                aif[2] = fma2(whif, (u64)b23.x, aif[2]); ago[2] = fma2(whgo, (u64)b23.x, ago[2]);
                aif[3] = fma2(wiif, (u64)a23.y, aif[3]); ago[3] = fma2(wigo, (u64)a23.y, ago[3]);
                aif[3] = fma2(whif, (u64)b23.y, aif[3]); ago[3] = fma2(whgo, (u64)b23.y, ago[3]);
                aif[4] = fma2(wiif, (u64)a45.x, aif[4]); ago[4] = fma2(wigo, (u64)a45.x, ago[4]);
                aif[4] = fma2(whif, (u64)b45.x, aif[4]); ago[4] = fma2(whgo, (u64)b45.x, ago[4]);
                aif[5] = fma2(wiif, (u64)a45.y, aif[5]); ago[5] = fma2(wigo, (u64)a45.y, ago[5]);
                aif[5] = fma2(whif, (u64)b45.y, aif[5]); ago[5] = fma2(whgo, (u64)b45.y, ago[5]);
                aif[6] = fma2(wiif, (u64)a67.x, aif[6]); ago[6] = fma2(wigo, (u64)a67.x, ago[6]);
                aif[6] = fma2(whif, (u64)b67.x, aif[6]); ago[6] = fma2(whgo, (u64)b67.x, ago[6]);
                aif[7] = fma2(wiif, (u64)a67.y, aif[7]); ago[7] = fma2(wigo, (u64)a67.y, ago[7]);
                aif[7] = fma2(whif, (u64)b67.y, aif[7]); ago[7] = fma2(whgo, (u64)b67.y, ago[7]);
            }
        }

#pragma unroll
        for (int m = 0; m < MH; m++) {
            float zi, zf, zg, zo;
            unpack2(aif[m], zi, zf);
            unpack2(ago[m], zg, zo);
            float ig = sigf(zi), fg = sigf(zf), gg = tanhf(zg), og = sigf(zo);
            float c = fmaf(fg, c2[m], ig * gg);
            c2[m] = c;
            float h = og * tanhf(c);
            h2out[j * HROW + mb + m] = pack2(h, h);
        }
        // next iteration's B1 orders h2out writes before next layer-1 reads
    }
    __syncthreads();

    // ---- FC epilogue ----
    const int fb = 1 ^ ((TT - 1) & 1);  // final h2 buffer index (0 for TT=200)
    if (tid < MM * OO) {
        int m = tid / OO;
        int o = tid % OO;
        const float* h2f = (const float*)(sh2 + fb * (HH * HROW));
        float s = b_fc[o];
#pragma unroll 4
        for (int k = 0; k < HH; k++)
            s = fmaf(h2f[k * (2 * HROW) + 2 * m], W_fc[o * HH + k], s);
        out[(row0 + m) * OO + o] = s;
    }
}

extern "C" void kernel_launch(void* const* d_in, const int* in_sizes, int n_in,
                              void* d_out, int out_size) {
    const float* x     = (const float*)d_in[0];
    const float* W_ih0 = (const float*)d_in[1];
    const float* W_hh0 = (const float*)d_in[2];
    const float* b_ih0 = (const float*)d_in[3];
    const float* b_hh0 = (const float*)d_in[4];
    const float* W_ih1 = (const float*)d_in[5];
    const float* W_hh1 = (const float*)d_in[6];
    const float* b_ih1 = (const float*)d_in[7];
    const float* b_hh1 = (const float*)d_in[8];
    const float* W_fc  = (const float*)d_in[9];
    const float* b_fc  = (const float*)d_in[10];
    float* out = (float*)d_out;

    const int smem_bytes = (2 * SH_LAYER) * 8 + MM * DD * 4;
    cudaFuncSetAttribute(lstm_kernel, cudaFuncAttributeMaxDynamicSharedMemorySize,
                         smem_bytes);

    prep_kernel<<<256, 256>>>(W_hh0, W_ih1, W_hh1, b_ih0, b_hh0, b_ih1, b_hh1);
    lstm_kernel<<<NCTA, 512, smem_bytes>>>(x, W_ih0, W_fc, b_fc, out);
}

// round 6
// speedup vs baseline: 1.0673x; 1.0673x over previous
#include <cuda_runtime.h>

// Problem constants
#define BB 2048
#define TT 200
#define DD 4
#define HH 256
#define GG 1024        // 4*H, gate order i,f,g,o
#define MM 16          // batch rows per CTA
#define NCTA (BB / MM) // 128 CTAs
#define MH 8           // rows per thread (one batch half)
#define OO 6
#define HROW 18        // u64 (dup-pair) slots per h row: 16 used + 2 pad (144B)
#define SH_LAYER (2 * HH * HROW)  // u64 count, one double-buffered layer
#define NK2 (HH / 2)   // 128 k-pairs

typedef unsigned long long u64;

// k-paired, gate-pair-interleaved weights.
// Entry [(k2*2+pp)*HH + j] = longlong2 { pack2(w_g0[2k2][j],   w_g1[2k2][j]),
//                                        pack2(w_g0[2k2+1][j], w_g1[2k2+1][j]) }
// pp=0 -> gates (i,f), pp=1 -> gates (g,o).  +2*HH pad rows for prefetch overrun.
__device__ longlong2 g_W0p[(NK2 * 2 + 2) * HH];   // W_hh0
__device__ longlong2 g_W1ip[(NK2 * 2 + 2) * HH];  // W_ih1
__device__ longlong2 g_W1hp[(NK2 * 2 + 2) * HH];  // W_hh1
__device__ float g_b0[GG];
__device__ float g_b1[GG];

// ---- packed f32x2 helpers ----
__device__ __forceinline__ u64 fma2(u64 a, u64 b, u64 c) {
    u64 d;
    asm("fma.rn.f32x2 %0, %1, %2, %3;" : "=l"(d) : "l"(a), "l"(b), "l"(c));
    return d;
}
__device__ __forceinline__ u64 pack2(float a, float b) {
    u64 d;
    asm("mov.b64 %0, {%1, %2};" : "=l"(d)
        : "r"(__float_as_uint(a)), "r"(__float_as_uint(b)));
    return d;
}
__device__ __forceinline__ u64 dup2(float v) {
    u64 d;
    unsigned r = __float_as_uint(v);
    asm("mov.b64 %0, {%1, %1};" : "=l"(d) : "r"(r));
    return d;
}
__device__ __forceinline__ void unpack2(u64 v, float& a, float& b) {
    unsigned x, y;
    asm("mov.b64 {%0, %1}, %2;" : "=r"(x), "=r"(y) : "l"(v));
    a = __uint_as_float(x);
    b = __uint_as_float(y);
}
// fast, saturating-safe activations (rel err ~1e-6, budget is 1e-3)
__device__ __forceinline__ float sigf(float x) {
    return __fdividef(1.0f, 1.0f + __expf(-x));
}
__device__ __forceinline__ float tanh_fast(float x) {
    float ax = fabsf(x);
    float e = __expf(-2.0f * ax);          // in (0,1], no overflow
    float t = __fdividef(1.0f - e, 1.0f + e);
    return copysignf(t, x);
}

// -------- prep: build k-paired gate-pair weights + combined biases --------
__global__ void prep_kernel(const float* __restrict__ W_hh0,
                            const float* __restrict__ W_ih1,
                            const float* __restrict__ W_hh1,
                            const float* __restrict__ b_ih0,
                            const float* __restrict__ b_hh0,
                            const float* __restrict__ b_ih1,
                            const float* __restrict__ b_hh1) {
    int idx = blockIdx.x * blockDim.x + threadIdx.x;
    int stride = gridDim.x * blockDim.x;
    for (int t = idx; t < NK2 * 2 * HH; t += stride) {
        int j = t & (HH - 1);
        int pp = (t >> 8) & 1;
        int k2 = t >> 9;
        int g0 = 2 * pp * HH + j;  // gate i (pp=0) or g (pp=1)
        int g1 = g0 + HH;          // gate f (pp=0) or o (pp=1)
        int ka = 2 * k2, kb = 2 * k2 + 1;
        longlong2 v;
        v.x = (long long)pack2(W_hh0[g0 * HH + ka], W_hh0[g1 * HH + ka]);
        v.y = (long long)pack2(W_hh0[g0 * HH + kb], W_hh0[g1 * HH + kb]);
        g_W0p[t] = v;
        v.x = (long long)pack2(W_ih1[g0 * HH + ka], W_ih1[g1 * HH + ka]);
        v.y = (long long)pack2(W_ih1[g0 * HH + kb], W_ih1[g1 * HH + kb]);
        g_W1ip[t] = v;
        v.x = (long long)pack2(W_hh1[g0 * HH + ka], W_hh1[g1 * HH + ka]);
        v.y = (long long)pack2(W_hh1[g0 * HH + kb], W_hh1[g1 * HH + kb]);
        g_W1hp[t] = v;
    }
    if (idx < GG) {
        g_b0[idx] = b_ih0[idx] + b_hh0[idx];
        g_b1[idx] = b_ih1[idx] + b_hh1[idx];
    }
}

// -------- main LSTM kernel: 512 threads = 256 hidden units x 2 batch halves --------
__global__ __launch_bounds__(512, 1)
void lstm_kernel(const float* __restrict__ x,
                 const float* __restrict__ W_ih0,
                 const float* __restrict__ W_fc,
                 const float* __restrict__ b_fc,
                 float* __restrict__ out) {
    extern __shared__ u64 dsm[];
    u64* sh1 = dsm;                             // [2][HH][HROW] layer0 h (dup pairs)
    u64* sh2 = dsm + SH_LAYER;                  // [2][HH][HROW] layer1 h
    float* xsall = (float*)(dsm + 2 * SH_LAYER);  // [MM][TT*DD] staged input

    const int tid  = threadIdx.x;
    const int j    = tid & (HH - 1);  // hidden unit
    const int half = tid >> 8;        // batch half (warp-uniform)
    const int mb   = half * MH;       // first dup-pair slot for this thread
    const int row0 = blockIdx.x * MM;

    // ---- stage the CTA's entire x tile: 16 rows x 800 contiguous floats ----
    {
        const int nf4 = MM * TT * DD / 4;  // 3200 float4
        for (int i = tid; i < nf4; i += 512) {
            int m = i / (TT * DD / 4);
            int c = i % (TT * DD / 4);
            reinterpret_cast<float4*>(xsall + m * (TT * DD))[c] =
                reinterpret_cast<const float4*>(x + (size_t)(row0 + m) * (TT * DD))[c];
        }
    }

    // Per-thread constants: fma2-packed input weights + bias pairs
    u64 wif0[DD], wgo0[DD];
#pragma unroll
    for (int d = 0; d < DD; d++) {
        wif0[d] = pack2(W_ih0[j * DD + d], W_ih0[(j + HH) * DD + d]);
        wgo0[d] = pack2(W_ih0[(j + 2 * HH) * DD + d], W_ih0[(j + 3 * HH) * DD + d]);
    }
    const u64 bif0 = pack2(g_b0[j], g_b0[j + HH]);
    const u64 bgo0 = pack2(g_b0[j + 2 * HH], g_b0[j + 3 * HH]);
    const u64 bif1 = pack2(g_b1[j], g_b1[j + HH]);
    const u64 bgo1 = pack2(g_b1[j + 2 * HH], g_b1[j + 3 * HH]);

    float c1[MH], c2[MH];
#pragma unroll
    for (int m = 0; m < MH; m++) {
        c1[m] = 0.0f;
        c2[m] = 0.0f;
        sh1[j * HROW + mb + m] = 0ull;  // buffer 0
        sh2[j * HROW + mb + m] = 0ull;
    }
    __syncthreads();

    for (int t = 0; t < TT; t++) {
        const int inb = t & 1;
        const int outb = inb ^ 1;
        const u64* h1in = sh1 + inb * (HH * HROW);
        u64* h1out      = sh1 + outb * (HH * HROW);
        const u64* h2in = sh2 + inb * (HH * HROW);
        u64* h2out      = sh2 + outb * (HH * HROW);

        // ================= Layer 0 =================
        u64 aif[MH], ago[MH];
#pragma unroll
        for (int m = 0; m < MH; m++) {
            u64 zif = bif0, zgo = bgo0;
            const float* xp = xsall + (mb + m) * (TT * DD) + t * DD;
#pragma unroll
            for (int d = 0; d < DD; d++) {
                u64 xd = dup2(xp[d]);
                zif = fma2(wif0[d], xd, zif);
                zgo = fma2(wgo0[d], xd, zgo);
            }
            aif[m] = zif;
            ago[m] = zgo;
        }

        {
            const longlong2* p = g_W0p + j;
            longlong2 w_if = p[0];
            longlong2 w_go = p[HH];
#pragma unroll 4
            for (int k2 = 0; k2 < NK2; k2++) {
                longlong2 cw_if = w_if, cw_go = w_go;
                // prefetch next k-pair (pad rows absorb the last overrun)
                w_if = p[(k2 + 1) * 2 * HH];
                w_go = p[(k2 + 1) * 2 * HH + HH];
                const longlong2* ha =
                    (const longlong2*)(h1in + (2 * k2) * HROW + mb);
                const longlong2* hb =
                    (const longlong2*)(h1in + (2 * k2 + 1) * HROW + mb);
                longlong2 a0 = ha[0], a1 = ha[1], a2 = ha[2], a3 = ha[3];
                longlong2 b0 = hb[0], b1 = hb[1], b2 = hb[2], b3 = hb[3];
                aif[0] = fma2((u64)cw_if.x, (u64)a0.x, aif[0]); ago[0] = fma2((u64)cw_go.x, (u64)a0.x, ago[0]);
                aif[1] = fma2((u64)cw_if.x, (u64)a0.y, aif[1]); ago[1] = fma2((u64)cw_go.x, (u64)a0.y, ago[1]);
                aif[2] = fma2((u64)cw_if.x, (u64)a1.x, aif[2]); ago[2] = fma2((u64)cw_go.x, (u64)a1.x, ago[2]);
                aif[3] = fma2((u64)cw_if.x, (u64)a1.y, aif[3]); ago[3] = fma2((u64)cw_go.x, (u64)a1.y, ago[3]);
                aif[4] = fma2((u64)cw_if.x, (u64)a2.x, aif[4]); ago[4] = fma2((u64)cw_go.x, (u64)a2.x, ago[4]);
                aif[5] = fma2((u64)cw_if.x, (u64)a2.y, aif[5]); ago[5] = fma2((u64)cw_go.x, (u64)a2.y, ago[5]);
                aif[6] = fma2((u64)cw_if.x, (u64)a3.x, aif[6]); ago[6] = fma2((u64)cw_go.x, (u64)a3.x, ago[6]);
                aif[7] = fma2((u64)cw_if.x, (u64)a3.y, aif[7]); ago[7] = fma2((u64)cw_go.x, (u64)a3.y, ago[7]);
                aif[0] = fma2((u64)cw_if.y, (u64)b0.x, aif[0]); ago[0] = fma2((u64)cw_go.y, (u64)b0.x, ago[0]);
                aif[1] = fma2((u64)cw_if.y, (u64)b0.y, aif[1]); ago[1] = fma2((u64)cw_go.y, (u64)b0.y, ago[1]);
                aif[2] = fma2((u64)cw_if.y, (u64)b1.x, aif[2]); ago[2] = fma2((u64)cw_go.y, (u64)b1.x, ago[2]);
                aif[3] = fma2((u64)cw_if.y, (u64)b1.y, aif[3]); ago[3] = fma2((u64)cw_go.y, (u64)b1.y, ago[3]);
                aif[4] = fma2((u64)cw_if.y, (u64)b2.x, aif[4]); ago[4] = fma2((u64)cw_go.y, (u64)b2.x, ago[4]);
                aif[5] = fma2((u64)cw_if.y, (u64)b2.y, aif[5]); ago[5] = fma2((u64)cw_go.y, (u64)b2.y, ago[5]);
                aif[6] = fma2((u64)cw_if.y, (u64)b3.x, aif[6]); ago[6] = fma2((u64)cw_go.y, (u64)b3.x, ago[6]);
                aif[7] = fma2((u64)cw_if.y, (u64)b3.y, aif[7]); ago[7] = fma2((u64)cw_go.y, (u64)b3.y, ago[7]);
            }
        }

        // activations + cell update, write dup'd h1 (STS.128 pairs)
#pragma unroll
        for (int i = 0; i < MH / 2; i++) {
            float zi0, zf0, zg0, zo0, zi1, zf1, zg1, zo1;
            unpack2(aif[2 * i], zi0, zf0);
            unpack2(ago[2 * i], zg0, zo0);
            unpack2(aif[2 * i + 1], zi1, zf1);
            unpack2(ago[2 * i + 1], zg1, zo1);
            float cA = fmaf(sigf(zf0), c1[2 * i], sigf(zi0) * tanh_fast(zg0));
            float cB = fmaf(sigf(zf1), c1[2 * i + 1], sigf(zi1) * tanh_fast(zg1));
            c1[2 * i] = cA;
            c1[2 * i + 1] = cB;
            float hA = sigf(zo0) * tanh_fast(cA);
            float hB = sigf(zo1) * tanh_fast(cB);
            longlong2 st;
            st.x = (long long)dup2(hA);
            st.y = (long long)dup2(hB);
            ((longlong2*)(h1out + j * HROW + mb))[i] = st;
        }
        __syncthreads();  // B2: h1out(t) + h2out(t-1) visible

        // ================= Layer 1 =================
#pragma unroll
        for (int m = 0; m < MH; m++) {
            aif[m] = bif1;
            ago[m] = bgo1;
        }

        {
            const longlong2* pi = g_W1ip + j;
            const longlong2* ph = g_W1hp + j;
            longlong2 wi_if = pi[0], wi_go = pi[HH];
            longlong2 wh_if = ph[0], wh_go = ph[HH];
#pragma unroll 2
            for (int k2 = 0; k2 < NK2; k2++) {
                longlong2 ci_if = wi_if, ci_go = wi_go, ch_if = wh_if, ch_go = wh_go;
                wi_if = pi[(k2 + 1) * 2 * HH];
                wi_go = pi[(k2 + 1) * 2 * HH + HH];
                wh_if = ph[(k2 + 1) * 2 * HH];
                wh_go = ph[(k2 + 1) * 2 * HH + HH];
                const longlong2* xa = (const longlong2*)(h1out + (2 * k2) * HROW + mb);
                const longlong2* xb = (const longlong2*)(h1out + (2 * k2 + 1) * HROW + mb);
                const longlong2* ya = (const longlong2*)(h2in + (2 * k2) * HROW + mb);
                const longlong2* yb = (const longlong2*)(h2in + (2 * k2 + 1) * HROW + mb);
                longlong2 p0 = xa[0], p1 = xa[1], p2 = xa[2], p3 = xa[3];
                longlong2 q0 = xb[0], q1 = xb[1], q2 = xb[2], q3 = xb[3];
                longlong2 r0 = ya[0], r1 = ya[1], r2 = ya[2], r3 = ya[3];
                longlong2 s0 = yb[0], s1 = yb[1], s2 = yb[2], s3 = yb[3];
                aif[0] = fma2((u64)ci_if.x, (u64)p0.x, aif[0]); ago[0] = fma2((u64)ci_go.x, (u64)p0.x, ago[0]);
                aif[0] = fma2((u64)ch_if.x, (u64)r0.x, aif[0]); ago[0] = fma2((u64)ch_go.x, (u64)r0.x, ago[0]);
                aif[1] = fma2((u64)ci_if.x, (u64)p0.y, aif[1]); ago[1] = fma2((u64)ci_go.x, (u64)p0.y, ago[1]);
                aif[1] = fma2((u64)ch_if.x, (u64)r0.y, aif[1]); ago[1] = fma2((u64)ch_go.x, (u64)r0.y, ago[1]);
                aif[2] = fma2((u64)ci_if.x, (u64)p1.x, aif[2]); ago[2] = fma2((u64)ci_go.x, (u64)p1.x, ago[2]);
                aif[2] = fma2((u64)ch_if.x, (u64)r1.x, aif[2]); ago[2] = fma2((u64)ch_go.x, (u64)r1.x, ago[2]);
                aif[3] = fma2((u64)ci_if.x, (u64)p1.y, aif[3]); ago[3] = fma2((u64)ci_go.x, (u64)p1.y, ago[3]);
                aif[3] = fma2((u64)ch_if.x, (u64)r1.y, aif[3]); ago[3] = fma2((u64)ch_go.x, (u64)r1.y, ago[3]);
                aif[4] = fma2((u64)ci_if.x, (u64)p2.x, aif[4]); ago[4] = fma2((u64)ci_go.x, (u64)p2.x, ago[4]);
                aif[4] = fma2((u64)ch_if.x, (u64)r2.x, aif[4]); ago[4] = fma2((u64)ch_go.x, (u64)r2.x, ago[4]);
                aif[5] = fma2((u64)ci_if.x, (u64)p2.y, aif[5]); ago[5] = fma2((u64)ci_go.x, (u64)p2.y, ago[5]);
                aif[5] = fma2((u64)ch_if.x, (u64)r2.y, aif[5]); ago[5] = fma2((u64)ch_go.x, (u64)r2.y, ago[5]);
                aif[6] = fma2((u64)ci_if.x, (u64)p3.x, aif[6]); ago[6] = fma2((u64)ci_go.x, (u64)p3.x, ago[6]);
                aif[6] = fma2((u64)ch_if.x, (u64)r3.x, aif[6]); ago[6] = fma2((u64)ch_go.x, (u64)r3.x, ago[6]);
                aif[7] = fma2((u64)ci_if.x, (u64)p3.y, aif[7]); ago[7] = fma2((u64)ci_go.x, (u64)p3.y, ago[7]);
                aif[7] = fma2((u64)ch_if.x, (u64)r3.y, aif[7]); ago[7] = fma2((u64)ch_go.x, (u64)r3.y, ago[7]);
                aif[0] = fma2((u64)ci_if.y, (u64)q0.x, aif[0]); ago[0] = fma2((u64)ci_go.y, (u64)q0.x, ago[0]);
                aif[0] = fma2((u64)ch_if.y, (u64)s0.x, aif[0]); ago[0] = fma2((u64)ch_go.y, (u64)s0.x, ago[0]);
                aif[1] = fma2((u64)ci_if.y, (u64)q0.y, aif[1]); ago[1] = fma2((u64)ci_go.y, (u64)q0.y, ago[1]);
                aif[1] = fma2((u64)ch_if.y, (u64)s0.y, aif[1]); ago[1] = fma2((u64)ch_go.y, (u64)s0.y, ago[1]);
                aif[2] = fma2((u64)ci_if.y, (u64)q1.x, aif[2]); ago[2] = fma2((u64)ci_go.y, (u64)q1.x, ago[2]);
                aif[2] = fma2((u64)ch_if.y, (u64)s1.x, aif[2]); ago[2] = fma2((u64)ch_go.y, (u64)s1.x, ago[2]);
                aif[3] = fma2((u64)ci_if.y, (u64)q1.y, aif[3]); ago[3] = fma2((u64)ci_go.y, (u64)q1.y, ago[3]);
                aif[3] = fma2((u64)ch_if.y, (u64)s1.y, aif[3]); ago[3] = fma2((u64)ch_go.y, (u64)s1.y, ago[3]);
                aif[4] = fma2((u64)ci_if.y, (u64)q2.x, aif[4]); ago[4] = fma2((u64)ci_go.y, (u64)q2.x, ago[4]);
                aif[4] = fma2((u64)ch_if.y, (u64)s2.x, aif[4]); ago[4] = fma2((u64)ch_go.y, (u64)s2.x, ago[4]);
                aif[5] = fma2((u64)ci_if.y, (u64)q2.y, aif[5]); ago[5] = fma2((u64)ci_go.y, (u64)q2.y, ago[5]);
                aif[5] = fma2((u64)ch_if.y, (u64)s2.y, aif[5]); ago[5] = fma2((u64)ch_go.y, (u64)s2.y, ago[5]);
                aif[6] = fma2((u64)ci_if.y, (u64)q3.x, aif[6]); ago[6] = fma2((u64)ci_go.y, (u64)q3.x, ago[6]);
                aif[6] = fma2((u64)ch_if.y, (u64)s3.x, aif[6]); ago[6] = fma2((u64)ch_go.y, (u64)s3.x, ago[6]);
                aif[7] = fma2((u64)ci_if.y, (u64)q3.y, aif[7]); ago[7] = fma2((u64)ci_go.y, (u64)q3.y, ago[7]);
                aif[7] = fma2((u64)ch_if.y, (u64)s3.y, aif[7]); ago[7] = fma2((u64)ch_go.y, (u64)s3.y, ago[7]);
            }
        }

#pragma unroll
        for (int i = 0; i < MH / 2; i++) {
            float zi0, zf0, zg0, zo0, zi1, zf1, zg1, zo1;
            unpack2(aif[2 * i], zi0, zf0);
            unpack2(ago[2 * i], zg0, zo0);
            unpack2(aif[2 * i + 1], zi1, zf1);
            unpack2(ago[2 * i + 1], zg1, zo1);
            float cA = fmaf(sigf(zf0), c2[2 * i], sigf(zi0) * tanh_fast(zg0));
            float cB = fmaf(sigf(zf1), c2[2 * i + 1], sigf(zi1) * tanh_fast(zg1));
            c2[2 * i] = cA;
            c2[2 * i + 1] = cB;
            float hA = sigf(zo0) * tanh_fast(cA);
            float hB = sigf(zo1) * tanh_fast(cB);
            longlong2 st;
            st.x = (long long)dup2(hA);
            st.y = (long long)dup2(hB);
            ((longlong2*)(h2out + j * HROW + mb))[i] = st;
        }
        __syncthreads();  // B1 for next step: h1in/h2in stable, h2out visible
    }

    // ---- FC epilogue ----
    const int fb = ((TT - 1) & 1) ^ 1;  // final h2 buffer (0 for TT=200)
    if (tid < MM * OO) {
        int m = tid / OO;
        int o = tid % OO;
        const float* h2f = (const float*)(sh2 + fb * (HH * HROW));
        float s = b_fc[o];
#pragma unroll 4
        for (int k = 0; k < HH; k++)
            s = fmaf(h2f[k * (2 * HROW) + 2 * m], W_fc[o * HH + k], s);
        out[(row0 + m) * OO + o] = s;
    }
}

extern "C" void kernel_launch(void* const* d_in, const int* in_sizes, int n_in,
                              void* d_out, int out_size) {
    const float* x     = (const float*)d_in[0];
    const float* W_ih0 = (const float*)d_in[1];
    const float* W_hh0 = (const float*)d_in[2];
    const float* b_ih0 = (const float*)d_in[3];
    const float* b_hh0 = (const float*)d_in[4];
    const float* W_ih1 = (const float*)d_in[5];
    const float* W_hh1 = (const float*)d_in[6];
    const float* b_ih1 = (const float*)d_in[7];
    const float* b_hh1 = (const float*)d_in[8];
    const float* W_fc  = (const float*)d_in[9];
    const float* b_fc  = (const float*)d_in[10];
    float* out = (float*)d_out;

    const int smem_bytes = (2 * SH_LAYER) * 8 + MM * TT * DD * 4;  // 147456 + 51200
    cudaFuncSetAttribute(lstm_kernel, cudaFuncAttributeMaxDynamicSharedMemorySize,
                         smem_bytes);

    prep_kernel<<<256, 256>>>(W_hh0, W_ih1, W_hh1, b_ih0, b_hh0, b_ih1, b_hh1);
    lstm_kernel<<<NCTA, 512, smem_bytes>>>(x, W_ih0, W_fc, b_fc, out);
}

// round 7
// speedup vs baseline: 1.1361x; 1.0644x over previous
#include <cuda_runtime.h>

// Problem constants
#define BB 2048
#define TT 200
#define DD 4
#define HH 256
#define GG 1024        // 4*H, gate order i,f,g,o
#define MM 16          // batch rows per CTA
#define NCTA (BB / MM) // 128 CTAs
#define MH 8           // rows per thread (one batch half)
#define OO 6
#define HROW 18        // u64 dup-pair slots per h row: 16 used + 2 pad (144B, 16B-aligned)
#define NK2 (HH / 2)   // 128 k-pairs
#define CPAD 20        // c-row stride in floats (80B, 16B-aligned)

typedef unsigned long long u64;

// ONE fused weight array: per k2, six HH-blocks of longlong2:
//   blk 0: hh0 (i,f)   blk 1: hh0 (g,o)
//   blk 2: ih1 (i,f)   blk 3: ih1 (g,o)
//   blk 4: hh1 (i,f)   blk 5: hh1 (g,o)
// entry [k2*6*HH + blk*HH + j] = { pack2(wg0[2k2][j], wg1[2k2][j]),
//                                  pack2(wg0[2k2+1][j], wg1[2k2+1][j]) }
__device__ longlong2 g_Wall[NK2 * 6 * HH];
__device__ float g_b0[GG];
__device__ float g_b1[GG];

// ---- packed f32x2 helpers ----
__device__ __forceinline__ u64 fma2(u64 a, u64 b, u64 c) {
    u64 d;
    asm("fma.rn.f32x2 %0, %1, %2, %3;" : "=l"(d) : "l"(a), "l"(b), "l"(c));
    return d;
}
__device__ __forceinline__ u64 pack2(float a, float b) {
    u64 d;
    asm("mov.b64 %0, {%1, %2};" : "=l"(d)
        : "r"(__float_as_uint(a)), "r"(__float_as_uint(b)));
    return d;
}
__device__ __forceinline__ u64 dup2(float v) {
    u64 d;
    unsigned r = __float_as_uint(v);
    asm("mov.b64 %0, {%1, %1};" : "=l"(d) : "r"(r));
    return d;
}
__device__ __forceinline__ void unpack2(u64 v, float& a, float& b) {
    unsigned x, y;
    asm("mov.b64 {%0, %1}, %2;" : "=r"(x), "=r"(y) : "l"(v));
    a = __uint_as_float(x);
    b = __uint_as_float(y);
}
__device__ __forceinline__ float sigf(float x) {
    return __fdividef(1.0f, 1.0f + __expf(-x));
}
__device__ __forceinline__ float tanh_fast(float x) {
    float ax = fabsf(x);
    float e = __expf(-2.0f * ax);
    float t = __fdividef(1.0f - e, 1.0f + e);
    return copysignf(t, x);
}

// -------- prep: fused interleaved weights + combined biases --------
__global__ void prep_kernel(const float* __restrict__ W_hh0,
                            const float* __restrict__ W_ih1,
                            const float* __restrict__ W_hh1,
                            const float* __restrict__ b_ih0,
                            const float* __restrict__ b_hh0,
                            const float* __restrict__ b_ih1,
                            const float* __restrict__ b_hh1) {
    int idx = blockIdx.x * blockDim.x + threadIdx.x;
    int stride = gridDim.x * blockDim.x;
    const int total = NK2 * 6 * HH;
    for (int t = idx; t < total; t += stride) {
        int j = t & (HH - 1);
        int blk = (t >> 8) % 6;
        int k2 = t / (6 * HH);
        int pp = blk & 1;
        const float* mat = (blk < 2) ? W_hh0 : (blk < 4) ? W_ih1 : W_hh1;
        int g0 = 2 * pp * HH + j;  // gate i (pp=0) or g (pp=1)
        int g1 = g0 + HH;          // gate f or o
        int ka = 2 * k2, kb = 2 * k2 + 1;
        longlong2 v;
        v.x = (long long)pack2(mat[g0 * HH + ka], mat[g1 * HH + ka]);
        v.y = (long long)pack2(mat[g0 * HH + kb], mat[g1 * HH + kb]);
        g_Wall[t] = v;
    }
    if (idx < GG) {
        g_b0[idx] = b_ih0[idx] + b_hh0[idx];
        g_b1[idx] = b_ih1[idx] + b_hh1[idx];
    }
}

// per-k fma block: each dup'd h1 value feeds 4 fma2, each h2 value feeds 2
#define ROWK(m, HV, YV)                                                     \
    aif0[m] = fma2(w0if_s, (HV), aif0[m]);                                  \
    ago0[m] = fma2(w0go_s, (HV), ago0[m]);                                  \
    aif1[m] = fma2(w1iif_s, (HV), aif1[m]);                                 \
    ago1[m] = fma2(w1igo_s, (HV), ago1[m]);                                 \
    aif1[m] = fma2(w1hif_s, (YV), aif1[m]);                                 \
    ago1[m] = fma2(w1hgo_s, (YV), ago1[m]);

#define DO_K(HPTR, YPTR)                                                    \
    {                                                                       \
        const longlong2* _h = (const longlong2*)(HPTR);                     \
        const longlong2* _y = (const longlong2*)(YPTR);                     \
        longlong2 h01 = _h[0], h23 = _h[1], h45 = _h[2], h67 = _h[3];       \
        longlong2 y01 = _y[0], y23 = _y[1], y45 = _y[2], y67 = _y[3];       \
        ROWK(0, (u64)h01.x, (u64)y01.x)                                     \
        ROWK(1, (u64)h01.y, (u64)y01.y)                                     \
        ROWK(2, (u64)h23.x, (u64)y23.x)                                     \
        ROWK(3, (u64)h23.y, (u64)y23.y)                                     \
        ROWK(4, (u64)h45.x, (u64)y45.x)                                     \
        ROWK(5, (u64)h45.y, (u64)y45.y)                                     \
        ROWK(6, (u64)h67.x, (u64)y67.x)                                     \
        ROWK(7, (u64)h67.y, (u64)y67.y)                                     \
    }

// -------- main fused LSTM kernel: 512 threads = 256 units x 2 batch halves --------
__global__ __launch_bounds__(512, 1)
void lstm_kernel(const float* __restrict__ x,
                 const float* __restrict__ W_ih0,
                 const float* __restrict__ W_fc,
                 const float* __restrict__ b_fc,
                 float* __restrict__ out) {
    extern __shared__ u64 dsm[];
    u64* sh1 = dsm;                      // [2][HH][HROW] layer0 h (dup pairs)
    u64* sh2 = dsm + 2 * HH * HROW;      // [2][HH][HROW] layer1 h
    u64* sbias = sh2 + 2 * HH * HROW;    // [4][HH]: bif0,bgo0,bif1,bgo1
    u64* swih = sbias + 4 * HH;          // [8][HH]: (pp*4+d) -> packed W_ih0 pairs
    float* sc = (float*)(swih + 8 * HH); // [2][HH][CPAD] cell state
    float* xs = sc + 2 * HH * CPAD;      // [2][MM*DD] double-buffered x

    const int tid  = threadIdx.x;
    const int j    = tid & (HH - 1);  // hidden unit
    const int mb   = (tid >> 8) * MH; // first dup-pair slot (warp-uniform)
    const int row0 = blockIdx.x * MM;

    // ---- one-time init ----
    for (int i = tid; i < 4 * HH * HROW; i += 512) dsm[i] = 0ull;  // both h layers
    for (int i = tid; i < 2 * HH * CPAD; i += 512) sc[i] = 0.0f;
    if (tid < HH) {
        sbias[tid]          = pack2(g_b0[tid], g_b0[tid + HH]);
        sbias[HH + tid]     = pack2(g_b0[tid + 2 * HH], g_b0[tid + 3 * HH]);
        sbias[2 * HH + tid] = pack2(g_b1[tid], g_b1[tid + HH]);
        sbias[3 * HH + tid] = pack2(g_b1[tid + 2 * HH], g_b1[tid + 3 * HH]);
#pragma unroll
        for (int d = 0; d < DD; d++) {
            swih[d * HH + tid] =
                pack2(W_ih0[tid * DD + d], W_ih0[(tid + HH) * DD + d]);
            swih[(4 + d) * HH + tid] =
                pack2(W_ih0[(tid + 2 * HH) * DD + d], W_ih0[(tid + 3 * HH) * DD + d]);
        }
    }
    if (tid < MM * DD)
        xs[tid] = x[(size_t)(row0 + (tid >> 2)) * (TT * DD) + (tid & 3)];
    __syncthreads();

    // ---- 201 fused phases: phase t = layer0(t) + layer1(t-1) ----
    for (int t = 0; t <= TT; t++) {
        const u64* h1in = sh1 + ((t + 1) & 1) * (HH * HROW);
        u64* h1out      = sh1 + (t & 1) * (HH * HROW);
        const u64* h2in = sh2 + (t & 1) * (HH * HROW);
        u64* h2out      = sh2 + ((t + 1) & 1) * (HH * HROW);
        const float* xcur = xs + (t & 1) * (MM * DD);

        // prefetch next-phase x (warps 0-1 only)
        float xreg = 0.0f;
        const bool doPref = (tid < MM * DD) && (t + 1 < TT);
        if (doPref)
            xreg = x[(size_t)(row0 + (tid >> 2)) * (TT * DD) + (t + 1) * DD + (tid & 3)];

        // init accumulators: layer0 = bias + W_ih0*x(t); layer1 = bias
        u64 aif0[MH], ago0[MH], aif1[MH], ago1[MH];
        {
            u64 b0a = sbias[j], b0b = sbias[HH + j];
            u64 b1a = sbias[2 * HH + j], b1b = sbias[3 * HH + j];
            u64 wif[DD], wgo[DD];
#pragma unroll
            for (int d = 0; d < DD; d++) {
                wif[d] = swih[d * HH + j];
                wgo[d] = swih[(4 + d) * HH + j];
            }
#pragma unroll
            for (int m = 0; m < MH; m++) {
                u64 zif = b0a, zgo = b0b;
#pragma unroll
                for (int d = 0; d < DD; d++) {
                    u64 xd = dup2(xcur[(mb + m) * DD + d]);
                    zif = fma2(wif[d], xd, zif);
                    zgo = fma2(wgo[d], xd, zgo);
                }
                aif0[m] = zif;
                ago0[m] = zgo;
                aif1[m] = b1a;
                ago1[m] = b1b;
            }
        }

        // fused k-loop: 96 fma2 per k2, h1 loads shared between layers
        {
            const longlong2* wp = g_Wall + j;
            const u64* h1p = h1in + mb;
            const u64* h2p = h2in + mb;
#pragma unroll 1
            for (int k2 = 0; k2 < NK2; k2++) {
                longlong2 w0if = wp[0], w0go = wp[HH];
                longlong2 w1iif = wp[2 * HH], w1igo = wp[3 * HH];
                longlong2 w1hif = wp[4 * HH], w1hgo = wp[5 * HH];
                wp += 6 * HH;
                {
                    u64 w0if_s = (u64)w0if.x, w0go_s = (u64)w0go.x;
                    u64 w1iif_s = (u64)w1iif.x, w1igo_s = (u64)w1igo.x;
                    u64 w1hif_s = (u64)w1hif.x, w1hgo_s = (u64)w1hgo.x;
                    DO_K(h1p, h2p)
                }
                {
                    u64 w0if_s = (u64)w0if.y, w0go_s = (u64)w0go.y;
                    u64 w1iif_s = (u64)w1iif.y, w1igo_s = (u64)w1igo.y;
                    u64 w1hif_s = (u64)w1hif.y, w1hgo_s = (u64)w1hgo.y;
                    DO_K(h1p + HROW, h2p + HROW)
                }
                h1p += 2 * HROW;
                h2p += 2 * HROW;
            }
        }

        // ---- layer0 activation: h1(t) (skip on boundary phase t=TT) ----
        if (t < TT) {
            float* cr = sc + j * CPAD + mb;
#pragma unroll
            for (int i = 0; i < MH / 2; i++) {
                float zi0, zf0, zg0, zo0, zi1, zf1, zg1, zo1;
                unpack2(aif0[2 * i], zi0, zf0);
                unpack2(ago0[2 * i], zg0, zo0);
                unpack2(aif0[2 * i + 1], zi1, zf1);
                unpack2(ago0[2 * i + 1], zg1, zo1);
                float cA = fmaf(sigf(zf0), cr[2 * i], sigf(zi0) * tanh_fast(zg0));
                float cB = fmaf(sigf(zf1), cr[2 * i + 1], sigf(zi1) * tanh_fast(zg1));
                cr[2 * i] = cA;
                cr[2 * i + 1] = cB;
                longlong2 st;
                st.x = (long long)dup2(sigf(zo0) * tanh_fast(cA));
                st.y = (long long)dup2(sigf(zo1) * tanh_fast(cB));
                ((longlong2*)(h1out + j * HROW + mb))[i] = st;
            }
        }

        // ---- layer1 activation: h2(t-1) (skip on boundary phase t=0) ----
        if (t >= 1) {
            float* cr = sc + HH * CPAD + j * CPAD + mb;
#pragma unroll
            for (int i = 0; i < MH / 2; i++) {
                float zi0, zf0, zg0, zo0, zi1, zf1, zg1, zo1;
                unpack2(aif1[2 * i], zi0, zf0);
                unpack2(ago1[2 * i], zg0, zo0);
                unpack2(aif1[2 * i + 1], zi1, zf1);
                unpack2(ago1[2 * i + 1], zg1, zo1);
                float cA = fmaf(sigf(zf0), cr[2 * i], sigf(zi0) * tanh_fast(zg0));
                float cB = fmaf(sigf(zf1), cr[2 * i + 1], sigf(zi1) * tanh_fast(zg1));
                cr[2 * i] = cA;
                cr[2 * i + 1] = cB;
                longlong2 st;
                st.x = (long long)dup2(sigf(zo0) * tanh_fast(cA));
                st.y = (long long)dup2(sigf(zo1) * tanh_fast(cB));
                ((longlong2*)(h2out + j * HROW + mb))[i] = st;
            }
        }

        if (doPref) xs[((t + 1) & 1) * (MM * DD) + tid] = xreg;

        __syncthreads();  // single barrier per phase
    }

    // ---- FC epilogue: h2(199) lives in sh2 buffer 1 ----
    if (tid < MM * OO) {
        int m = tid / OO;
        int o = tid % OO;
        const float* h2f = (const float*)(sh2 + 1 * (HH * HROW));
        float s = b_fc[o];
#pragma unroll 4
        for (int k = 0; k < HH; k++)
            s = fmaf(h2f[(k * HROW + m) * 2], W_fc[o * HH + k], s);
        out[(row0 + m) * OO + o] = s;
    }
}

extern "C" void kernel_launch(void* const* d_in, const int* in_sizes, int n_in,
                              void* d_out, int out_size) {
    const float* x     = (const float*)d_in[0];
    const float* W_ih0 = (const float*)d_in[1];
    const float* W_hh0 = (const float*)d_in[2];
    const float* b_ih0 = (const float*)d_in[3];
    const float* b_hh0 = (const float*)d_in[4];
    const float* W_ih1 = (const float*)d_in[5];
    const float* W_hh1 = (const float*)d_in[6];
    const float* b_ih1 = (const float*)d_in[7];
    const float* b_hh1 = (const float*)d_in[8];
    const float* W_fc  = (const float*)d_in[9];
    const float* b_fc  = (const float*)d_in[10];
    float* out = (float*)d_out;

    // smem: sh1+sh2 (4*HH*HROW u64) + sbias (4*HH) + swih (8*HH) u64
    //       + sc (2*HH*CPAD) + xs (2*MM*DD) floats
    const int smem_bytes = (4 * HH * HROW + 12 * HH) * 8 +
                           (2 * HH * CPAD + 2 * MM * DD) * 4;  // 213,504 B
    cudaFuncSetAttribute(lstm_kernel, cudaFuncAttributeMaxDynamicSharedMemorySize,
                         smem_bytes);

    prep_kernel<<<256, 256>>>(W_hh0, W_ih1, W_hh1, b_ih0, b_hh0, b_ih1, b_hh1);
    lstm_kernel<<<NCTA, 512, smem_bytes>>>(x, W_ih0, W_fc, b_fc, out);
}